// round 1
// baseline (speedup 1.0000x reference)
#include <cuda_runtime.h>
#include <math.h>

#define B_ 4096
#define S_ 50
#define I_ 4
#define E_ 64

// hat scratch, layout (B, I, S, E) — 4096*4*50*64 floats = 209.7 MB
__device__ __align__(256) float g_hat[(size_t)B_ * I_ * S_ * E_];

// ---------------------------------------------------------------------------
// Kernel 1: hat[b, i, s, e] = sum_k item[b, s, k] * w[s, i*64+e, k]
// 50 batched GEMMs (per s): M=4096 (batch), N=256 (m = i*64+e), K=64.
// Block tile: 64 (batch) x 64 (m), full K=64. 256 threads, 4x4 microtile.
// ---------------------------------------------------------------------------
__global__ __launch_bounds__(256) void gemm_hat_kernel(
    const float* __restrict__ item,   // (B, S, E)
    const float* __restrict__ w)      // (1, S, I*E, E)
{
    __shared__ __align__(16) float Xs[64][68];  // [e][local b]
    __shared__ __align__(16) float Ws[64][68];  // [e][local m]

    const int s  = blockIdx.z;
    const int mt = blockIdx.y;     // interest index i
    const int bt = blockIdx.x;
    const int t  = threadIdx.x;

    const float* xg = item + (size_t)(bt * 64) * (S_ * E_) + (size_t)s * E_;
    const float* wg = w + (size_t)s * (I_ * E_ * E_) + (size_t)(mt * 64) * E_;

    #pragma unroll
    for (int c = 0; c < 4; ++c) {
        int f4   = t + c * 256;
        int row  = f4 >> 4;
        int col4 = f4 & 15;
        int e0   = col4 * 4;
        float4 xv = *(const float4*)(xg + (size_t)row * (S_ * E_) + e0);
        float4 wv = *(const float4*)(wg + row * E_ + e0);
        Xs[e0 + 0][row] = xv.x; Xs[e0 + 1][row] = xv.y;
        Xs[e0 + 2][row] = xv.z; Xs[e0 + 3][row] = xv.w;
        Ws[e0 + 0][row] = wv.x; Ws[e0 + 1][row] = wv.y;
        Ws[e0 + 2][row] = wv.z; Ws[e0 + 3][row] = wv.w;
    }
    __syncthreads();

    const int tx = t & 15;
    const int ty = t >> 4;
    const int ty4 = ty * 4, tx4 = tx * 4;

    float acc[4][4];
    #pragma unroll
    for (int i = 0; i < 4; ++i)
        #pragma unroll
        for (int j = 0; j < 4; ++j) acc[i][j] = 0.0f;

    #pragma unroll
    for (int e = 0; e < 64; ++e) {
        float4 a = *(const float4*)&Xs[e][ty4];
        float4 q = *(const float4*)&Ws[e][tx4];
        acc[0][0] += a.x * q.x; acc[0][1] += a.x * q.y; acc[0][2] += a.x * q.z; acc[0][3] += a.x * q.w;
        acc[1][0] += a.y * q.x; acc[1][1] += a.y * q.y; acc[1][2] += a.y * q.z; acc[1][3] += a.y * q.w;
        acc[2][0] += a.z * q.x; acc[2][1] += a.z * q.y; acc[2][2] += a.z * q.z; acc[2][3] += a.z * q.w;
        acc[3][0] += a.w * q.x; acc[3][1] += a.w * q.y; acc[3][2] += a.w * q.z; acc[3][3] += a.w * q.w;
    }

    #pragma unroll
    for (int i = 0; i < 4; ++i) {
        int b = bt * 64 + ty4 + i;
        size_t off = ((((size_t)b * I_ + mt) * S_ + s) * E_) + tx4;
        *(float4*)(g_hat + off) = make_float4(acc[i][0], acc[i][1], acc[i][2], acc[i][3]);
    }
}

// ---------------------------------------------------------------------------
// Kernel 2: dynamic routing. One warp per (b, i).
// ---------------------------------------------------------------------------
__global__ __launch_bounds__(32) void routing_kernel(
    const int* __restrict__ mask,    // (B, S)
    float* __restrict__ out)         // (B, I, E)
{
    __shared__ __align__(16) float hat_sm[64 * 65];   // rows 50..63 unused/garbage
    __shared__ float sw_sm[64];
    __shared__ float cap_sm[64];

    const int bi   = blockIdx.x;
    const int b    = bi >> 2;
    const int i    = bi & 3;
    const int lane = threadIdx.x;

    const float* hg = g_hat + ((size_t)b * I_ + i) * (S_ * E_);

    #pragma unroll
    for (int c = 0; c < 25; ++c) {
        int f4 = lane + c * 32;
        float4 v = *(const float4*)(hg + (size_t)f4 * 4);
        int elem = f4 * 4;
        int s = elem >> 6;
        int e = elem & 63;
        float* p = &hat_sm[s * 65 + e];
        p[0] = v.x; p[1] = v.y; p[2] = v.z; p[3] = v.w;
    }

    const int s0 = lane;
    const int s1 = lane + 32;
    const bool v1 = (s1 < S_);
    const float mk0 = (mask[b * S_ + s0] != 0) ? 1.0f : 0.0f;
    const float mk1 = (v1 && mask[b * S_ + s1] != 0) ? 1.0f : 0.0f;

    float cw0 = 0.0f, cw1 = 0.0f;
    float cap0 = 0.0f, cap1 = 0.0f;
    __syncwarp();

    #pragma unroll
    for (int it = 0; it < 3; ++it) {
        float x0 = cw0;
        float x1 = v1 ? cw1 : -1e30f;
        float mx = fmaxf(x0, x1);
        #pragma unroll
        for (int o = 16; o > 0; o >>= 1) mx = fmaxf(mx, __shfl_xor_sync(0xffffffffu, mx, o));
        float e0 = expf(x0 - mx);
        float e1 = v1 ? expf(x1 - mx) : 0.0f;
        float sm = e0 + e1;
        #pragma unroll
        for (int o = 16; o > 0; o >>= 1) sm += __shfl_xor_sync(0xffffffffu, sm, o);
        float inv = 1.0f / sm;
        sw_sm[s0] = e0 * inv * mk0;
        if (v1) sw_sm[s1] = e1 * inv * mk1;
        __syncwarp();

        cap0 = 0.0f; cap1 = 0.0f;
        #pragma unroll 10
        for (int s = 0; s < S_; ++s) {
            float wv = sw_sm[s];
            cap0 += wv * hat_sm[s * 65 + lane];
            cap1 += wv * hat_sm[s * 65 + 32 + lane];
        }

        float n = cap0 * cap0 + cap1 * cap1;
        #pragma unroll
        for (int o = 16; o > 0; o >>= 1) n += __shfl_xor_sync(0xffffffffu, n, o);
        float scale = (n / (1.0f + n)) * rsqrtf(n + 1e-9f);
        cap0 *= scale; cap1 *= scale;

        if (it < 2) {
            cap_sm[lane] = cap0;
            cap_sm[lane + 32] = cap1;
            __syncwarp();
            float d0 = 0.0f, d1 = 0.0f;
            #pragma unroll 16
            for (int e = 0; e < E_; ++e) {
                float cv = cap_sm[e];
                d0 += cv * hat_sm[s0 * 65 + e];
                d1 += cv * hat_sm[s1 * 65 + e];
            }
            cw0 += d0;
            if (v1) cw1 += d1;
            __syncwarp();
        }
    }

    float* og = out + ((size_t)b * I_ + i) * E_;
    og[lane] = cap0;
    og[lane + 32] = cap1;
}

extern "C" void kernel_launch(void* const* d_in, const int* in_sizes, int n_in,
                              void* d_out, int out_size)
{
    const float* item = (const float*)d_in[0];
    const int*   mask = (const int*)d_in[1];
    const float* w    = (const float*)d_in[2];
    float* out = (float*)d_out;

    gemm_hat_kernel<<<dim3(64, 4, 50), 256>>>(item, w);
    routing_kernel<<<B_ * I_, 32>>>(mask, out);
}

// round 2
// speedup vs baseline: 1.2808x; 1.2808x over previous
#include <cuda_runtime.h>
#include <math.h>

#define B_ 4096
#define S_ 50
#define I_ 4
#define E_ 64

typedef unsigned long long ull;

// hat scratch, layout (B, I, S, E) — 209.7 MB
__device__ __align__(256) float g_hat[(size_t)B_ * I_ * S_ * E_];

// ---- f32x2 helpers (packed dual fp32 FMA; exact fp32 semantics) -----------
__device__ __forceinline__ ull rep2(float x) {
    ull r; asm("mov.b64 %0, {%1, %1};" : "=l"(r) : "f"(x)); return r;
}
__device__ __forceinline__ void fma2(ull& d, ull a, ull b) {
    asm("fma.rn.f32x2 %0, %1, %2, %0;" : "+l"(d) : "l"(a), "l"(b));
}
__device__ __forceinline__ void unpack2(ull v, float& lo, float& hi) {
    asm("mov.b64 {%0, %1}, %2;" : "=f"(lo), "=f"(hi) : "l"(v));
}

// ---------------------------------------------------------------------------
// Kernel 1: hat[b, i, s, e] = sum_k item[b, s, k] * w[s, i*64+e, k]
// Per s: GEMM M=4096(b) x N=256(m=i*64+e) x K=64.
// Block tile 128(b) x 128(m), K-slabs of 32. 256 threads, 8x8 microtile,
// accumulators packed along b as f32x2 (FFMA2).
// ---------------------------------------------------------------------------
__global__ __launch_bounds__(256, 2) void gemm_hat_kernel(
    const float* __restrict__ item,   // (B, S, E)
    const float* __restrict__ w)      // (1, S, I*E, E)
{
    __shared__ __align__(16) float Xs[32][132];  // [k][local b]
    __shared__ __align__(16) float Ws[32][132];  // [k][local m]

    const int s  = blockIdx.z;
    const int mt = blockIdx.y;     // 0..1 (128 m's each)
    const int bt = blockIdx.x;     // 0..31 (128 b's each)
    const int t  = threadIdx.x;
    const int tx = t & 15;         // m microtile (x8)
    const int ty = t >> 4;         // b microtile (x8)

    ull acc[4][8];
    #pragma unroll
    for (int ip = 0; ip < 4; ++ip)
        #pragma unroll
        for (int j = 0; j < 8; ++j) acc[ip][j] = 0ull;

    const float* xg = item + (size_t)(bt * 128) * (S_ * E_) + (size_t)s * E_;
    const float* wg = w + (size_t)s * (I_ * E_ * E_) + (size_t)(mt * 128) * E_;

    #pragma unroll
    for (int kb = 0; kb < 64; kb += 32) {
        __syncthreads();
        // load 128x32 slabs of X and W, transposed into smem
        #pragma unroll
        for (int c = 0; c < 4; ++c) {
            int f4   = t + c * 256;    // 0..1023
            int row  = f4 >> 3;        // 0..127
            int e0   = (f4 & 7) * 4;   // 0..28
            float4 xv = *(const float4*)(xg + (size_t)row * (S_ * E_) + kb + e0);
            float4 wv = *(const float4*)(wg + row * E_ + kb + e0);
            Xs[e0 + 0][row] = xv.x; Xs[e0 + 1][row] = xv.y;
            Xs[e0 + 2][row] = xv.z; Xs[e0 + 3][row] = xv.w;
            Ws[e0 + 0][row] = wv.x; Ws[e0 + 1][row] = wv.y;
            Ws[e0 + 2][row] = wv.z; Ws[e0 + 3][row] = wv.w;
        }
        __syncthreads();

        #pragma unroll
        for (int k = 0; k < 32; ++k) {
            const ull* pa = (const ull*)&Xs[k][ty * 8];
            ull a0 = pa[0], a1 = pa[1], a2 = pa[2], a3 = pa[3];
            float4 qa = *(const float4*)&Ws[k][tx * 8];
            float4 qb = *(const float4*)&Ws[k][tx * 8 + 4];
            ull q0 = rep2(qa.x), q1 = rep2(qa.y), q2 = rep2(qa.z), q3 = rep2(qa.w);
            ull q4 = rep2(qb.x), q5 = rep2(qb.y), q6 = rep2(qb.z), q7 = rep2(qb.w);
            fma2(acc[0][0], a0, q0); fma2(acc[0][1], a0, q1); fma2(acc[0][2], a0, q2); fma2(acc[0][3], a0, q3);
            fma2(acc[0][4], a0, q4); fma2(acc[0][5], a0, q5); fma2(acc[0][6], a0, q6); fma2(acc[0][7], a0, q7);
            fma2(acc[1][0], a1, q0); fma2(acc[1][1], a1, q1); fma2(acc[1][2], a1, q2); fma2(acc[1][3], a1, q3);
            fma2(acc[1][4], a1, q4); fma2(acc[1][5], a1, q5); fma2(acc[1][6], a1, q6); fma2(acc[1][7], a1, q7);
            fma2(acc[2][0], a2, q0); fma2(acc[2][1], a2, q1); fma2(acc[2][2], a2, q2); fma2(acc[2][3], a2, q3);
            fma2(acc[2][4], a2, q4); fma2(acc[2][5], a2, q5); fma2(acc[2][6], a2, q6); fma2(acc[2][7], a2, q7);
            fma2(acc[3][0], a3, q0); fma2(acc[3][1], a3, q1); fma2(acc[3][2], a3, q2); fma2(acc[3][3], a3, q3);
            fma2(acc[3][4], a3, q4); fma2(acc[3][5], a3, q5); fma2(acc[3][6], a3, q6); fma2(acc[3][7], a3, q7);
        }
    }

    // store to g_hat (B, I, S, E)
    const int m  = mt * 128 + tx * 8;
    const int ii = m >> 6;
    const int e  = m & 63;
    #pragma unroll
    for (int ip = 0; ip < 4; ++ip) {
        float lo[8], hi[8];
        #pragma unroll
        for (int j = 0; j < 8; ++j) unpack2(acc[ip][j], lo[j], hi[j]);
        int b0 = bt * 128 + ty * 8 + ip * 2;
        size_t base0 = (((size_t)b0 * I_ + ii) * S_ + s) * E_ + e;
        size_t base1 = base0 + (size_t)I_ * S_ * E_;   // b0+1
        *(float4*)(g_hat + base0)     = make_float4(lo[0], lo[1], lo[2], lo[3]);
        *(float4*)(g_hat + base0 + 4) = make_float4(lo[4], lo[5], lo[6], lo[7]);
        *(float4*)(g_hat + base1)     = make_float4(hi[0], hi[1], hi[2], hi[3]);
        *(float4*)(g_hat + base1 + 4) = make_float4(hi[4], hi[5], hi[6], hi[7]);
    }
}

// ---------------------------------------------------------------------------
// Kernel 2: dynamic routing. One warp per (b, i). smem trimmed to 50 rows,
// occupancy forced to 16 CTAs/SM.
// ---------------------------------------------------------------------------
__global__ __launch_bounds__(32, 16) void routing_kernel(
    const int* __restrict__ mask,    // (B, S)
    float* __restrict__ out)         // (B, I, E)
{
    __shared__ __align__(16) float hat_sm[S_ * 65];   // 13000 B
    __shared__ float sw_sm[64];
    __shared__ float cap_sm[64];

    const int bi   = blockIdx.x;
    const int b    = bi >> 2;
    const int i    = bi & 3;
    const int lane = threadIdx.x;

    const int s0 = lane;
    const int s1 = lane + 32;
    const bool v1 = (s1 < S_);
    const int s1r = v1 ? s1 : 0;      // clamped row for unconditional smem reads

    // start mask loads early
    const float mk0 = (mask[b * S_ + s0] != 0) ? 1.0f : 0.0f;
    const float mk1 = (v1 && mask[b * S_ + s1] != 0) ? 1.0f : 0.0f;

    const float* hg = g_hat + ((size_t)b * I_ + i) * (S_ * E_);

    #pragma unroll
    for (int c = 0; c < 25; ++c) {
        int f4 = lane + c * 32;
        float4 v = *(const float4*)(hg + (size_t)f4 * 4);
        int elem = f4 * 4;
        int s = elem >> 6;
        int e = elem & 63;
        float* p = &hat_sm[s * 65 + e];
        p[0] = v.x; p[1] = v.y; p[2] = v.z; p[3] = v.w;
    }

    float cw0 = 0.0f, cw1 = 0.0f;
    float cap0 = 0.0f, cap1 = 0.0f;
    __syncwarp();

    #pragma unroll
    for (int it = 0; it < 3; ++it) {
        // softmax over all S positions, then mask to 0 (no renorm)
        float x0 = cw0;
        float x1 = v1 ? cw1 : -1e30f;
        float mx = fmaxf(x0, x1);
        #pragma unroll
        for (int o = 16; o > 0; o >>= 1) mx = fmaxf(mx, __shfl_xor_sync(0xffffffffu, mx, o));
        float e0 = expf(x0 - mx);
        float e1 = v1 ? expf(x1 - mx) : 0.0f;
        float sm = e0 + e1;
        #pragma unroll
        for (int o = 16; o > 0; o >>= 1) sm += __shfl_xor_sync(0xffffffffu, sm, o);
        float inv = 1.0f / sm;
        sw_sm[s0] = e0 * inv * mk0;
        sw_sm[s1] = e1 * inv * mk1;   // rows >= 50 never read
        __syncwarp();

        // cap[e] = sum_s sw[s] * hat[s][e]
        cap0 = 0.0f; cap1 = 0.0f;
        #pragma unroll 10
        for (int s = 0; s < S_; ++s) {
            float wv = sw_sm[s];
            cap0 += wv * hat_sm[s * 65 + lane];
            cap1 += wv * hat_sm[s * 65 + 32 + lane];
        }

        // squash
        float n = cap0 * cap0 + cap1 * cap1;
        #pragma unroll
        for (int o = 16; o > 0; o >>= 1) n += __shfl_xor_sync(0xffffffffu, n, o);
        float scale = (n / (1.0f + n)) * rsqrtf(n + 1e-9f);
        cap0 *= scale; cap1 *= scale;

        if (it < 2) {
            cap_sm[lane] = cap0;
            cap_sm[lane + 32] = cap1;
            __syncwarp();
            // delta[s] = sum_e hat[s][e] * cap[e]
            float d0 = 0.0f, d1 = 0.0f;
            #pragma unroll 16
            for (int e = 0; e < E_; ++e) {
                float cv = cap_sm[e];
                d0 += cv * hat_sm[s0 * 65 + e];
                d1 += cv * hat_sm[s1r * 65 + e];   // clamped row; result discarded if !v1
            }
            cw0 += d0;
            if (v1) cw1 += d1;
            __syncwarp();
        }
    }

    float* og = out + ((size_t)b * I_ + i) * E_;
    og[lane] = cap0;
    og[lane + 32] = cap1;
}

extern "C" void kernel_launch(void* const* d_in, const int* in_sizes, int n_in,
                              void* d_out, int out_size)
{
    const float* item = (const float*)d_in[0];   // (4096, 50, 64) fp32
    const int*   mask = (const int*)d_in[1];     // (4096, 50) int32
    const float* w    = (const float*)d_in[2];   // (1, 50, 256, 64) fp32
    float* out = (float*)d_out;                  // (4096, 4, 64) fp32

    gemm_hat_kernel<<<dim3(32, 2, 50), 256>>>(item, w);
    routing_kernel<<<B_ * I_, 32>>>(mask, out);
}

// round 5
// speedup vs baseline: 1.6527x; 1.2904x over previous
#include <cuda_runtime.h>
#include <cuda_bf16.h>
#include <math.h>
#include <stdint.h>

#define B_ 4096
#define S_ 50
#define I_ 4
#define E_ 64

// hat scratch, layout (B, I, S, E) — fp32, 209.7 MB
__device__ __align__(256) float g_hat[(size_t)B_ * I_ * S_ * E_];

// ============================================================================
// helpers
// ============================================================================
__device__ __forceinline__ uint32_t smem_u32(const void* p) {
    uint32_t a;
    asm("{ .reg .u64 t; cvta.to.shared.u64 t, %1; cvt.u32.u64 %0, t; }" : "=r"(a) : "l"(p));
    return a;
}

__device__ __forceinline__ void ldsm4(uint32_t* r, uint32_t addr) {
    asm volatile("ldmatrix.sync.aligned.m8n8.x4.shared.b16 {%0,%1,%2,%3}, [%4];"
                 : "=r"(r[0]), "=r"(r[1]), "=r"(r[2]), "=r"(r[3]) : "r"(addr));
}

__device__ __forceinline__ void mma_bf16(float* d, const uint32_t* a, uint32_t b0, uint32_t b1) {
    asm volatile("mma.sync.aligned.m16n8k16.row.col.f32.bf16.bf16.f32 "
                 "{%0,%1,%2,%3}, {%4,%5,%6,%7}, {%8,%9}, {%0,%1,%2,%3};"
                 : "+f"(d[0]), "+f"(d[1]), "+f"(d[2]), "+f"(d[3])
                 : "r"(a[0]), "r"(a[1]), "r"(a[2]), "r"(a[3]), "r"(b0), "r"(b1));
}

// hi/lo bf16 split of two floats, packed as bf16x2 words
__device__ __forceinline__ void split_pack(float a, float b, uint32_t& hi, uint32_t& lo) {
    __nv_bfloat16 ha = __float2bfloat16(a);
    __nv_bfloat16 hb = __float2bfloat16(b);
    __nv_bfloat16 la = __float2bfloat16(a - __bfloat162float(ha));
    __nv_bfloat16 lb = __float2bfloat16(b - __bfloat162float(hb));
    __nv_bfloat162 hp = __nv_bfloat162(ha, hb);
    __nv_bfloat162 lp = __nv_bfloat162(la, lb);
    hi = *reinterpret_cast<uint32_t*>(&hp);
    lo = *reinterpret_cast<uint32_t*>(&lp);
}

// ----------------------------------------------------------------------------
// smem: 4 tiles of 128 rows x 64 bf16 (128 B/row), XOR-swizzled for ldmatrix.
// Same 64 KB is reused as a 128x128 fp32 epilogue stage.
// ----------------------------------------------------------------------------
#define SA_H 0
#define SA_L 16384
#define SB_H 32768
#define SB_L 49152
#define SMEM_GEMM 65536

__device__ __forceinline__ uint32_t swz(int row, int colb) {
    return (uint32_t)(row * 128 + (colb ^ ((row & 7) << 4)));
}

// ============================================================================
// Kernel 1: hat = item @ w^T via mma.sync bf16 split-2 (hi*hi + hi*lo + lo*hi).
// Per CTA: one s, 128 b x 128 m, K=64. 8 warps, warp tile 32(b) x 64(m).
// grid = (32 b-tiles, 2 m-tiles, 50 s)
// ============================================================================
__global__ __launch_bounds__(256, 2) void hat_mma_kernel(
    const float* __restrict__ item,   // (B, S, E)
    const float* __restrict__ w)      // (1, S, I*E, E)
{
    extern __shared__ __align__(1024) char smem[];
    const uint32_t sb = smem_u32(smem);
    const int t    = threadIdx.x;
    const int lane = t & 31;
    const int wid  = t >> 5;
    const int wy   = wid >> 1;     // 0..3, 32-row b strip
    const int wx   = wid & 1;      // 0..1, 64-col m strip
    const int bt = blockIdx.x;
    const int mt = blockIdx.y;
    const int s  = blockIdx.z;

    // ---- load + split A (item) and B (w) tiles: each 128 rows x 64 k
    const float* ag = item + (size_t)(bt * 128) * (S_ * E_) + (size_t)s * E_;
    const float* bg = w + (size_t)s * (I_ * E_ * E_) + (size_t)(mt * 128) * E_;
    #pragma unroll
    for (int c = 0; c < 8; ++c) {
        int f4 = t + c * 256;          // 0..2047
        int r  = f4 >> 4;              // 0..127
        int k0 = (f4 & 15) * 4;        // 0..60
        uint32_t off = swz(r, k0 * 2);

        float4 av = *(const float4*)(ag + (size_t)r * (S_ * E_) + k0);
        uint32_t h01, l01, h23, l23;
        split_pack(av.x, av.y, h01, l01);
        split_pack(av.z, av.w, h23, l23);
        *(uint2*)(smem + SA_H + off) = make_uint2(h01, h23);
        *(uint2*)(smem + SA_L + off) = make_uint2(l01, l23);

        float4 bv = *(const float4*)(bg + (size_t)r * E_ + k0);
        split_pack(bv.x, bv.y, h01, l01);
        split_pack(bv.z, bv.w, h23, l23);
        *(uint2*)(smem + SB_H + off) = make_uint2(h01, h23);
        *(uint2*)(smem + SB_L + off) = make_uint2(l01, l23);
    }
    __syncthreads();

    float acc[2][8][4];
    #pragma unroll
    for (int mi = 0; mi < 2; ++mi)
        #pragma unroll
        for (int j = 0; j < 8; ++j)
            #pragma unroll
            for (int q = 0; q < 4; ++q) acc[mi][j][q] = 0.0f;

    const int rsub = (lane & 7) + (lane & 8);   // row-within-16 for ldsm x4
    const int csub = (lane >> 4) << 4;          // 0 or 16 col bytes

    // pass p: 0 = AH*BH, 1 = AH*BL, 2 = AL*BH
    #pragma unroll
    for (int p = 0; p < 3; ++p) {
        const uint32_t abase = sb + ((p == 2) ? SA_L : SA_H);
        const uint32_t bbase = sb + ((p == 1) ? SB_L : SB_H);
        #pragma unroll
        for (int ks = 0; ks < 4; ++ks) {
            const int kb = ks * 32 + csub;
            uint32_t af[2][4], bf[4][4];
            #pragma unroll
            for (int mi = 0; mi < 2; ++mi) {
                int r = wy * 32 + mi * 16 + rsub;
                ldsm4(af[mi], abase + swz(r, kb));
            }
            #pragma unroll
            for (int nb = 0; nb < 4; ++nb) {
                int n = wx * 64 + nb * 16 + rsub;
                ldsm4(bf[nb], bbase + swz(n, kb));
            }
            #pragma unroll
            for (int mi = 0; mi < 2; ++mi)
                #pragma unroll
                for (int j = 0; j < 8; ++j)
                    mma_bf16(acc[mi][j], af[mi], bf[j >> 1][j & 1], bf[j >> 1][2 + (j & 1)]);
        }
    }

    // ---- epilogue: stage fp32 in smem (reuses all 64 KB), coalesced write
    __syncthreads();
    float* stage = (float*)smem;   // 128 x 128 fp32
    #pragma unroll
    for (int mi = 0; mi < 2; ++mi) {
        int row = wy * 32 + mi * 16 + (lane >> 2);
        #pragma unroll
        for (int j = 0; j < 8; ++j) {
            int col = wx * 64 + j * 8 + (lane & 3) * 2;
            *(float2*)&stage[row * 128 + col]       = make_float2(acc[mi][j][0], acc[mi][j][1]);
            *(float2*)&stage[(row + 8) * 128 + col] = make_float2(acc[mi][j][2], acc[mi][j][3]);
        }
    }
    __syncthreads();

    #pragma unroll
    for (int it = 0; it < 16; ++it) {
        int idx = t + it * 256;        // 0..4095 float4 chunks
        int row = idx >> 5;            // 0..127
        int ch  = idx & 31;            // 0..31
        int b = bt * 128 + row;
        int m = mt * 128 + ch * 4;
        int i = m >> 6;
        int e = m & 63;
        float4 v = *(float4*)&stage[row * 128 + ch * 4];
        *(float4*)(g_hat + (((size_t)b * I_ + i) * S_ + s) * E_ + e) = v;
    }
}

// ============================================================================
// Kernel 2: dynamic routing. 64 threads per (b, i): thread-per-e for cap,
// thread-per-s for delta.
// ============================================================================
__device__ __forceinline__ float wred_max(float v) {
    #pragma unroll
    for (int o = 16; o > 0; o >>= 1) v = fmaxf(v, __shfl_xor_sync(0xffffffffu, v, o));
    return v;
}
__device__ __forceinline__ float wred_sum(float v) {
    #pragma unroll
    for (int o = 16; o > 0; o >>= 1) v += __shfl_xor_sync(0xffffffffu, v, o);
    return v;
}

__global__ __launch_bounds__(64, 16) void routing_kernel(
    const int* __restrict__ mask,    // (B, S)
    float* __restrict__ out)         // (B, I, E)
{
    __shared__ __align__(16) float hat_sm[S_ * 68];
    __shared__ float sw_sm[64];
    __shared__ __align__(16) float cap_sm[64];
    __shared__ float red_sm[4];

    const int bi   = blockIdx.x;
    const int b    = bi >> 2;
    const int i    = bi & 3;
    const int t    = threadIdx.x;    // 0..63
    const int wid  = t >> 5;
    const int lane = t & 31;

    const float mk = (t < S_ && mask[b * S_ + t] != 0) ? 1.0f : 0.0f;

    const float* hg = g_hat + ((size_t)b * I_ + i) * (S_ * E_);
    #pragma unroll
    for (int c = 0; c < 13; ++c) {
        int f4 = t + c * 64;
        if (f4 < 800) {
            float4 v = *(const float4*)(hg + (size_t)f4 * 4);
            int elem = f4 * 4;
            int s = elem >> 6;
            int e = elem & 63;
            *(float4*)&hat_sm[s * 68 + e] = v;
        }
    }

    float cw = 0.0f, cap = 0.0f;
    __syncthreads();

    #pragma unroll
    for (int it = 0; it < 3; ++it) {
        // softmax over all 50 s, then masked to 0 (no renorm)
        float x = (t < S_) ? cw : -1e30f;
        float wm = wred_max(x);
        if (lane == 0) red_sm[wid] = wm;
        __syncthreads();
        float mx = fmaxf(red_sm[0], red_sm[1]);
        float ex = (t < S_) ? expf(x - mx) : 0.0f;
        float ws = wred_sum(ex);
        if (lane == 0) red_sm[2 + wid] = ws;
        __syncthreads();
        float inv = 1.0f / (red_sm[2] + red_sm[3]);
        sw_sm[t] = ex * inv * mk;      // rows >= 50 never read
        __syncthreads();

        // cap[e=t] = sum_s sw[s] * hat[s][t]  (2-way split chain)
        float c0 = 0.0f, c1 = 0.0f;
        #pragma unroll
        for (int s = 0; s < S_ - 1; s += 2) {
            c0 = fmaf(sw_sm[s],     hat_sm[s * 68 + t],       c0);
            c1 = fmaf(sw_sm[s + 1], hat_sm[(s + 1) * 68 + t], c1);
        }
        float c = c0 + c1;

        // squash
        float ns = wred_sum(c * c);
        if (lane == 0) red_sm[wid] = ns;
        __syncthreads();
        float n = red_sm[0] + red_sm[1];
        float scale = (n / (1.0f + n)) * rsqrtf(n + 1e-9f);
        cap = c * scale;

        if (it < 2) {
            cap_sm[t] = cap;
            __syncthreads();
            // delta[s=t] = sum_e hat[t][e] * cap[e]
            if (t < S_) {
                const float4* h4 = (const float4*)&hat_sm[t * 68];
                const float4* c4 = (const float4*)cap_sm;
                float d0 = 0.0f, d1 = 0.0f;
                #pragma unroll
                for (int e4 = 0; e4 < 16; e4 += 2) {
                    float4 hv = h4[e4], cv = c4[e4];
                    d0 = fmaf(hv.x, cv.x, d0); d0 = fmaf(hv.y, cv.y, d0);
                    d0 = fmaf(hv.z, cv.z, d0); d0 = fmaf(hv.w, cv.w, d0);
                    float4 hv2 = h4[e4 + 1], cv2 = c4[e4 + 1];
                    d1 = fmaf(hv2.x, cv2.x, d1); d1 = fmaf(hv2.y, cv2.y, d1);
                    d1 = fmaf(hv2.z, cv2.z, d1); d1 = fmaf(hv2.w, cv2.w, d1);
                }
                cw += d0 + d1;
            }
            __syncthreads();
        }
    }

    out[((size_t)b * I_ + i) * E_ + t] = cap;
}

extern "C" void kernel_launch(void* const* d_in, const int* in_sizes, int n_in,
                              void* d_out, int out_size)
{
    const float* item = (const float*)d_in[0];   // (4096, 50, 64) fp32
    const int*   mask = (const int*)d_in[1];     // (4096, 50) int32
    const float* w    = (const float*)d_in[2];   // (1, 50, 256, 64) fp32
    float* out = (float*)d_out;                  // (4096, 4, 64) fp32

    cudaFuncSetAttribute(hat_mma_kernel, cudaFuncAttributeMaxDynamicSharedMemorySize,
                         SMEM_GEMM);
    hat_mma_kernel<<<dim3(32, 2, 50), 256, SMEM_GEMM>>>(item, w);
    routing_kernel<<<B_ * I_, 64>>>(mask, out);
}

// round 7
// speedup vs baseline: 1.9193x; 1.1613x over previous
#include <cuda_runtime.h>
#include <cuda_bf16.h>
#include <math.h>
#include <stdint.h>

#define B_ 4096
#define S_ 50
#define I_ 4
#define E_ 64

// hat scratch, layout (B, I, S, E) — fp32, 209.7 MB
__device__ __align__(256) float g_hat[(size_t)B_ * I_ * S_ * E_];

// pre-split bf16 hi/lo copies of item and w
#define ITEM_N ((size_t)B_ * S_ * E_)      // 13,107,200
#define W_N    ((size_t)S_ * I_ * E_ * E_)  // 819,200
__device__ __align__(256) __nv_bfloat16 g_item_h[ITEM_N];
__device__ __align__(256) __nv_bfloat16 g_item_l[ITEM_N];
__device__ __align__(256) __nv_bfloat16 g_w_h[W_N];
__device__ __align__(256) __nv_bfloat16 g_w_l[W_N];

// ============================================================================
// helpers
// ============================================================================
__device__ __forceinline__ uint32_t smem_u32(const void* p) {
    uint32_t a;
    asm("{ .reg .u64 t; cvta.to.shared.u64 t, %1; cvt.u32.u64 %0, t; }" : "=r"(a) : "l"(p));
    return a;
}

__device__ __forceinline__ void ldsm4(uint32_t* r, uint32_t addr) {
    asm volatile("ldmatrix.sync.aligned.m8n8.x4.shared.b16 {%0,%1,%2,%3}, [%4];"
                 : "=r"(r[0]), "=r"(r[1]), "=r"(r[2]), "=r"(r[3]) : "r"(addr));
}

__device__ __forceinline__ void mma_bf16(float* d, const uint32_t* a, uint32_t b0, uint32_t b1) {
    asm volatile("mma.sync.aligned.m16n8k16.row.col.f32.bf16.bf16.f32 "
                 "{%0,%1,%2,%3}, {%4,%5,%6,%7}, {%8,%9}, {%0,%1,%2,%3};"
                 : "+f"(d[0]), "+f"(d[1]), "+f"(d[2]), "+f"(d[3])
                 : "r"(a[0]), "r"(a[1]), "r"(a[2]), "r"(a[3]), "r"(b0), "r"(b1));
}

__device__ __forceinline__ void split_pack(float a, float b, uint32_t& hi, uint32_t& lo) {
    __nv_bfloat16 ha = __float2bfloat16(a);
    __nv_bfloat16 hb = __float2bfloat16(b);
    __nv_bfloat16 la = __float2bfloat16(a - __bfloat162float(ha));
    __nv_bfloat16 lb = __float2bfloat16(b - __bfloat162float(hb));
    __nv_bfloat162 hp = __nv_bfloat162(ha, hb);
    __nv_bfloat162 lp = __nv_bfloat162(la, lb);
    hi = *reinterpret_cast<uint32_t*>(&hp);
    lo = *reinterpret_cast<uint32_t*>(&lp);
}

// ============================================================================
// Kernel 0: split fp32 -> bf16 hi/lo into the device globals (no host
// symbol-address lookups). which = 0: item, 1: w.
// ============================================================================
__global__ __launch_bounds__(256) void split_kernel(
    const float4* __restrict__ src, int n4, int which)
{
    int idx = blockIdx.x * 256 + threadIdx.x;
    if (idx >= n4) return;
    float4 v = src[idx];
    uint32_t h01, l01, h23, l23;
    split_pack(v.x, v.y, h01, l01);
    split_pack(v.z, v.w, h23, l23);
    uint2* dh = (which == 0) ? (uint2*)g_item_h : (uint2*)g_w_h;
    uint2* dl = (which == 0) ? (uint2*)g_item_l : (uint2*)g_w_l;
    dh[idx] = make_uint2(h01, h23);
    dl[idx] = make_uint2(l01, l23);
}

// ----------------------------------------------------------------------------
// smem: 4 tiles of 128 rows x 64 bf16 (128 B/row), XOR-swizzled for ldmatrix
// ----------------------------------------------------------------------------
#define SA_H 0
#define SA_L 16384
#define SB_H 32768
#define SB_L 49152
#define SMEM_GEMM 65536

__device__ __forceinline__ uint32_t swz(int row, int colb) {
    return (uint32_t)(row * 128 + (colb ^ ((row & 7) << 4)));
}

// ============================================================================
// Kernel 1: hat = item @ w^T via mma.sync bf16 split-2 (hi*hi + hi*lo + lo*hi).
// Per CTA: one s, 128 b x 128 m, K=64. 8 warps, warp tile 32(b) x 64(m).
// Inputs are pre-split bf16; epilogue writes fragments directly to g_hat.
// grid = (32 b-tiles, 2 m-tiles, 50 s)
// ============================================================================
__global__ __launch_bounds__(256, 2) void hat_mma_kernel()
{
    extern __shared__ __align__(1024) char smem[];
    const uint32_t sb = smem_u32(smem);
    const int t    = threadIdx.x;
    const int lane = t & 31;
    const int wid  = t >> 5;
    const int wy   = wid >> 1;     // 0..3, 32-row b strip
    const int wx   = wid & 1;      // 0..1, 64-col m strip
    const int bt = blockIdx.x;
    const int mt = blockIdx.y;
    const int s  = blockIdx.z;

    // ---- load tiles (bf16, no conversion). Each tile: 128 rows x 128 B.
    {
        const __nv_bfloat16* ah = g_item_h + (size_t)(bt * 128) * (S_ * E_) + (size_t)s * E_;
        const __nv_bfloat16* al = g_item_l + (size_t)(bt * 128) * (S_ * E_) + (size_t)s * E_;
        const __nv_bfloat16* bh = g_w_h + ((size_t)s * (I_ * E_) + mt * 128) * E_;
        const __nv_bfloat16* bl = g_w_l + ((size_t)s * (I_ * E_) + mt * 128) * E_;
        #pragma unroll
        for (int c = 0; c < 4; ++c) {
            int f  = t + c * 256;       // 0..1023 16B chunks
            int r  = f >> 3;            // 0..127
            int ch = f & 7;             // 0..7
            uint32_t off = swz(r, ch * 16);
            size_t ga = (size_t)r * (S_ * E_) + ch * 8;
            *(uint4*)(smem + SA_H + off) = *(const uint4*)(ah + ga);
            *(uint4*)(smem + SA_L + off) = *(const uint4*)(al + ga);
            size_t gb = (size_t)r * E_ + ch * 8;
            *(uint4*)(smem + SB_H + off) = *(const uint4*)(bh + gb);
            *(uint4*)(smem + SB_L + off) = *(const uint4*)(bl + gb);
        }
    }
    __syncthreads();

    float acc[2][8][4];
    #pragma unroll
    for (int mi = 0; mi < 2; ++mi)
        #pragma unroll
        for (int j = 0; j < 8; ++j)
            #pragma unroll
            for (int q = 0; q < 4; ++q) acc[mi][j][q] = 0.0f;

    const int rsub = (lane & 7) + (lane & 8);
    const int csub = (lane >> 4) << 4;

    // pass p: 0 = AH*BH, 1 = AH*BL, 2 = AL*BH
    #pragma unroll
    for (int p = 0; p < 3; ++p) {
        const uint32_t abase = sb + ((p == 2) ? SA_L : SA_H);
        const uint32_t bbase = sb + ((p == 1) ? SB_L : SB_H);
        #pragma unroll
        for (int ks = 0; ks < 4; ++ks) {
            const int kb = ks * 32 + csub;
            uint32_t af[2][4], bf[4][4];
            #pragma unroll
            for (int mi = 0; mi < 2; ++mi) {
                int r = wy * 32 + mi * 16 + rsub;
                ldsm4(af[mi], abase + swz(r, kb));
            }
            #pragma unroll
            for (int nb = 0; nb < 4; ++nb) {
                int n = wx * 64 + nb * 16 + rsub;
                ldsm4(bf[nb], bbase + swz(n, kb));
            }
            #pragma unroll
            for (int mi = 0; mi < 2; ++mi)
                #pragma unroll
                for (int j = 0; j < 8; ++j)
                    mma_bf16(acc[mi][j], af[mi], bf[j >> 1][j & 1], bf[j >> 1][2 + (j & 1)]);
        }
    }

    // ---- epilogue: direct fragment writes (32B-sector coalesced)
    const size_t bstride = (size_t)I_ * S_ * E_;   // +1 in b
    #pragma unroll
    for (int mi = 0; mi < 2; ++mi) {
        int row = wy * 32 + mi * 16 + (lane >> 2);
        int b   = bt * 128 + row;
        #pragma unroll
        for (int j = 0; j < 8; ++j) {
            int m = mt * 128 + wx * 64 + j * 8 + (lane & 3) * 2;
            int i = m >> 6;
            int e = m & 63;
            size_t off = (((size_t)b * I_ + i) * S_ + s) * E_ + e;
            *(float2*)(g_hat + off)               = make_float2(acc[mi][j][0], acc[mi][j][1]);
            *(float2*)(g_hat + off + 8 * bstride) = make_float2(acc[mi][j][2], acc[mi][j][3]);
        }
    }
}

// ============================================================================
// Kernel 2: dynamic routing. 64 threads per (b, i). Each thread keeps its
// hat column (50 values) in registers for the cap matvec; smem hat used only
// for the delta (row-dot) loop.
// ============================================================================
__device__ __forceinline__ float wred_max(float v) {
    #pragma unroll
    for (int o = 16; o > 0; o >>= 1) v = fmaxf(v, __shfl_xor_sync(0xffffffffu, v, o));
    return v;
}
__device__ __forceinline__ float wred_sum(float v) {
    #pragma unroll
    for (int o = 16; o > 0; o >>= 1) v += __shfl_xor_sync(0xffffffffu, v, o);
    return v;
}

__global__ __launch_bounds__(64) void routing_kernel(
    const int* __restrict__ mask,    // (B, S)
    float* __restrict__ out)         // (B, I, E)
{
    __shared__ __align__(16) float hat_sm[S_ * 68];
    __shared__ float sw_sm[64];
    __shared__ __align__(16) float cap_sm[64];
    __shared__ float red_sm[4];

    const int bi   = blockIdx.x;
    const int b    = bi >> 2;
    const int i    = bi & 3;
    const int t    = threadIdx.x;    // 0..63
    const int wid  = t >> 5;
    const int lane = t & 31;

    const float mk = (t < S_ && mask[b * S_ + t] != 0) ? 1.0f : 0.0f;

    const float* hg = g_hat + ((size_t)b * I_ + i) * (S_ * E_);
    #pragma unroll
    for (int c = 0; c < 13; ++c) {
        int f4 = t + c * 64;
        if (f4 < 800) {
            float4 v = *(const float4*)(hg + (size_t)f4 * 4);
            int elem = f4 * 4;
            int s = elem >> 6;
            int e = elem & 63;
            *(float4*)&hat_sm[s * 68 + e] = v;
        }
    }
    __syncthreads();

    // hoist this thread's hat column into registers (read once)
    float h[S_];
    #pragma unroll
    for (int s = 0; s < S_; ++s) h[s] = hat_sm[s * 68 + t];

    float cw = 0.0f, cap = 0.0f;

    #pragma unroll
    for (int it = 0; it < 3; ++it) {
        // softmax over all 50 s, then masked to 0 (no renorm)
        float x = (t < S_) ? cw : -1e30f;
        float wm = wred_max(x);
        if (lane == 0) red_sm[wid] = wm;
        __syncthreads();
        float mx = fmaxf(red_sm[0], red_sm[1]);
        float ex = (t < S_) ? expf(x - mx) : 0.0f;
        float ws = wred_sum(ex);
        if (lane == 0) red_sm[2 + wid] = ws;
        __syncthreads();
        float inv = 1.0f / (red_sm[2] + red_sm[3]);
        sw_sm[t] = ex * inv * mk;      // rows >= 50 never read
        __syncthreads();

        // cap[e=t] = sum_s sw[s] * h[s]   (hat from registers, 2-way chain)
        float c0 = 0.0f, c1 = 0.0f;
        #pragma unroll
        for (int s = 0; s < S_ - 1; s += 2) {
            c0 = fmaf(sw_sm[s],     h[s],     c0);
            c1 = fmaf(sw_sm[s + 1], h[s + 1], c1);
        }
        float c = c0 + c1;

        // squash
        float ns = wred_sum(c * c);
        if (lane == 0) red_sm[wid] = ns;
        __syncthreads();
        float n = red_sm[0] + red_sm[1];
        float scale = (n / (1.0f + n)) * rsqrtf(n + 1e-9f);
        cap = c * scale;

        if (it < 2) {
            cap_sm[t] = cap;
            __syncthreads();
            // delta[s=t] = sum_e hat[t][e] * cap[e]  (smem rows)
            if (t < S_) {
                const float4* h4 = (const float4*)&hat_sm[t * 68];
                const float4* c4 = (const float4*)cap_sm;
                float d0 = 0.0f, d1 = 0.0f;
                #pragma unroll
                for (int e4 = 0; e4 < 16; e4 += 2) {
                    float4 hv = h4[e4], cv = c4[e4];
                    d0 = fmaf(hv.x, cv.x, d0); d0 = fmaf(hv.y, cv.y, d0);
                    d0 = fmaf(hv.z, cv.z, d0); d0 = fmaf(hv.w, cv.w, d0);
                    float4 hv2 = h4[e4 + 1], cv2 = c4[e4 + 1];
                    d1 = fmaf(hv2.x, cv2.x, d1); d1 = fmaf(hv2.y, cv2.y, d1);
                    d1 = fmaf(hv2.z, cv2.z, d1); d1 = fmaf(hv2.w, cv2.w, d1);
                }
                cw += d0 + d1;
            }
            __syncthreads();
        }
    }

    out[((size_t)b * I_ + i) * E_ + t] = cap;
}

extern "C" void kernel_launch(void* const* d_in, const int* in_sizes, int n_in,
                              void* d_out, int out_size)
{
    const float* item = (const float*)d_in[0];   // (4096, 50, 64) fp32
    const int*   mask = (const int*)d_in[1];     // (4096, 50) int32
    const float* w    = (const float*)d_in[2];   // (1, 50, 256, 64) fp32
    float* out = (float*)d_out;                  // (4096, 4, 64) fp32

    const int item4 = (int)(ITEM_N / 4);
    const int w4    = (int)(W_N / 4);
    split_kernel<<<(item4 + 255) / 256, 256>>>((const float4*)item, item4, 0);
    split_kernel<<<(w4 + 255) / 256, 256>>>((const float4*)w, w4, 1);

    cudaFuncSetAttribute(hat_mma_kernel, cudaFuncAttributeMaxDynamicSharedMemorySize,
                         SMEM_GEMM);
    hat_mma_kernel<<<dim3(32, 2, 50), 256, SMEM_GEMM>>>();
    routing_kernel<<<B_ * I_, 64>>>(mask, out);
}

// round 8
// speedup vs baseline: 1.9883x; 1.0359x over previous
#include <cuda_runtime.h>
#include <cuda_bf16.h>
#include <math.h>
#include <stdint.h>

#define B_ 4096
#define S_ 50
#define I_ 4
#define E_ 64

// hat scratch, layout (B, I, S, E) — fp32, 209.7 MB
__device__ __align__(256) float g_hat[(size_t)B_ * I_ * S_ * E_];

// pre-split bf16 hi/lo copies of w only (item is split in-kernel)
#define W_N ((size_t)S_ * I_ * E_ * E_)  // 819,200
__device__ __align__(256) __nv_bfloat16 g_w_h[W_N];
__device__ __align__(256) __nv_bfloat16 g_w_l[W_N];

// ============================================================================
// helpers
// ============================================================================
__device__ __forceinline__ uint32_t smem_u32(const void* p) {
    uint32_t a;
    asm("{ .reg .u64 t; cvta.to.shared.u64 t, %1; cvt.u32.u64 %0, t; }" : "=r"(a) : "l"(p));
    return a;
}

__device__ __forceinline__ void ldsm4(uint32_t* r, uint32_t addr) {
    asm volatile("ldmatrix.sync.aligned.m8n8.x4.shared.b16 {%0,%1,%2,%3}, [%4];"
                 : "=r"(r[0]), "=r"(r[1]), "=r"(r[2]), "=r"(r[3]) : "r"(addr));
}

__device__ __forceinline__ void mma_bf16(float* d, const uint32_t* a, uint32_t b0, uint32_t b1) {
    asm volatile("mma.sync.aligned.m16n8k16.row.col.f32.bf16.bf16.f32 "
                 "{%0,%1,%2,%3}, {%4,%5,%6,%7}, {%8,%9}, {%0,%1,%2,%3};"
                 : "+f"(d[0]), "+f"(d[1]), "+f"(d[2]), "+f"(d[3])
                 : "r"(a[0]), "r"(a[1]), "r"(a[2]), "r"(a[3]), "r"(b0), "r"(b1));
}

__device__ __forceinline__ void split_pack(float a, float b, uint32_t& hi, uint32_t& lo) {
    __nv_bfloat16 ha = __float2bfloat16(a);
    __nv_bfloat16 hb = __float2bfloat16(b);
    __nv_bfloat16 la = __float2bfloat16(a - __bfloat162float(ha));
    __nv_bfloat16 lb = __float2bfloat16(b - __bfloat162float(hb));
    __nv_bfloat162 hp = __nv_bfloat162(ha, hb);
    __nv_bfloat162 lp = __nv_bfloat162(la, lb);
    hi = *reinterpret_cast<uint32_t*>(&hp);
    lo = *reinterpret_cast<uint32_t*>(&lp);
}

// ============================================================================
// Kernel 0: split w fp32 -> bf16 hi/lo (element order preserved)
// ============================================================================
__global__ __launch_bounds__(256) void split_w_kernel(const float4* __restrict__ src, int n4)
{
    int idx = blockIdx.x * 256 + threadIdx.x;
    if (idx >= n4) return;
    float4 v = src[idx];
    uint32_t h01, l01, h23, l23;
    split_pack(v.x, v.y, h01, l01);
    split_pack(v.z, v.w, h23, l23);
    ((uint2*)g_w_h)[idx] = make_uint2(h01, h23);
    ((uint2*)g_w_l)[idx] = make_uint2(l01, l23);
}

// ----------------------------------------------------------------------------
// smem layout (bytes): A_hi 8K | A_lo 8K | B_hi 32K | B_lo 32K  = 80K
// All tiles: rows x 128B, XOR-swizzled for ldmatrix.
// ----------------------------------------------------------------------------
#define SA_H 0
#define SA_L 8192
#define SB_H 16384
#define SB_L 49152
#define SMEM_GEMM 81920

__device__ __forceinline__ uint32_t swz(int row, int colb) {
    return (uint32_t)(row * 128 + (colb ^ ((row & 7) << 4)));
}

// ============================================================================
// Kernel 1: hat = item @ w^T via mma.sync bf16 split-2 (hi*hi + hi*lo + lo*hi).
// Per CTA: one s, 64 b x 256 m (full m!), K=64. item read fp32, split in-kernel.
// 8 warps: 2 (b) x 4 (m) of 32x64 warp tiles. grid = (64 b-tiles, 50 s)
// ============================================================================
__global__ __launch_bounds__(256, 2) void hat_mma_kernel(
    const float* __restrict__ item)   // (B, S, E) fp32
{
    extern __shared__ __align__(1024) char smem[];
    const uint32_t sb = smem_u32(smem);
    const int t    = threadIdx.x;
    const int lane = t & 31;
    const int wid  = t >> 5;
    const int wy   = wid >> 2;     // 0..1, 32-row b strip
    const int wx   = wid & 3;      // 0..3, 64-col m strip
    const int bt = blockIdx.x;
    const int s  = blockIdx.y;

    // ---- A: 64 rows x 64 k fp32 -> split bf16 hi/lo into smem
    {
        const float* ag = item + (size_t)(bt * 64) * (S_ * E_) + (size_t)s * E_;
        #pragma unroll
        for (int c = 0; c < 4; ++c) {
            int f4 = t + c * 256;          // 0..1023
            int r  = f4 >> 4;              // 0..63
            int k0 = (f4 & 15) * 4;        // 0..60
            float4 v = *(const float4*)(ag + (size_t)r * (S_ * E_) + k0);
            uint32_t h01, l01, h23, l23;
            split_pack(v.x, v.y, h01, l01);
            split_pack(v.z, v.w, h23, l23);
            uint32_t off = swz(r, k0 * 2);
            *(uint2*)(smem + SA_H + off) = make_uint2(h01, h23);
            *(uint2*)(smem + SA_L + off) = make_uint2(l01, l23);
        }
    }
    // ---- B: 256 rows x 64 k, pre-split bf16
    {
        const __nv_bfloat16* bh = g_w_h + (size_t)s * (I_ * E_ * E_);
        const __nv_bfloat16* bl = g_w_l + (size_t)s * (I_ * E_ * E_);
        #pragma unroll
        for (int c = 0; c < 8; ++c) {
            int f  = t + c * 256;       // 0..2047 16B chunks
            int r  = f >> 3;            // 0..255
            int ch = f & 7;             // 0..7
            uint32_t off = swz(r, ch * 16);
            size_t g = (size_t)r * E_ + ch * 8;
            *(uint4*)(smem + SB_H + off) = *(const uint4*)(bh + g);
            *(uint4*)(smem + SB_L + off) = *(const uint4*)(bl + g);
        }
    }
    __syncthreads();

    float acc[2][8][4];
    #pragma unroll
    for (int mi = 0; mi < 2; ++mi)
        #pragma unroll
        for (int j = 0; j < 8; ++j)
            #pragma unroll
            for (int q = 0; q < 4; ++q) acc[mi][j][q] = 0.0f;

    const int rsub = (lane & 7) + (lane & 8);
    const int csub = (lane >> 4) << 4;

    // pass p: 0 = AH*BH, 1 = AH*BL, 2 = AL*BH
    #pragma unroll
    for (int p = 0; p < 3; ++p) {
        const uint32_t abase = sb + ((p == 2) ? SA_L : SA_H);
        const uint32_t bbase = sb + ((p == 1) ? SB_L : SB_H);
        #pragma unroll
        for (int ks = 0; ks < 4; ++ks) {
            const int kb = ks * 32 + csub;
            uint32_t af[2][4], bf[4][4];
            #pragma unroll
            for (int mi = 0; mi < 2; ++mi) {
                int r = wy * 32 + mi * 16 + rsub;
                ldsm4(af[mi], abase + swz(r, kb));
            }
            #pragma unroll
            for (int nb = 0; nb < 4; ++nb) {
                int n = wx * 64 + nb * 16 + rsub;
                ldsm4(bf[nb], bbase + swz(n, kb));
            }
            #pragma unroll
            for (int mi = 0; mi < 2; ++mi)
                #pragma unroll
                for (int j = 0; j < 8; ++j)
                    mma_bf16(acc[mi][j], af[mi], bf[j >> 1][j & 1], bf[j >> 1][2 + (j & 1)]);
        }
    }

    // ---- epilogue: direct fragment writes (32B-sector coalesced)
    const size_t bstride = (size_t)I_ * S_ * E_;   // +1 in b
    #pragma unroll
    for (int mi = 0; mi < 2; ++mi) {
        int row = wy * 32 + mi * 16 + (lane >> 2);
        int b   = bt * 64 + row;
        #pragma unroll
        for (int j = 0; j < 8; ++j) {
            int m = wx * 64 + j * 8 + (lane & 3) * 2;
            int i = m >> 6;
            int e = m & 63;
            size_t off = (((size_t)b * I_ + i) * S_ + s) * E_ + e;
            *(float2*)(g_hat + off)               = make_float2(acc[mi][j][0], acc[mi][j][1]);
            *(float2*)(g_hat + off + 8 * bstride) = make_float2(acc[mi][j][2], acc[mi][j][3]);
        }
    }
}

// ============================================================================
// Kernel 2: dynamic routing. 64 threads per (b, i). Thread t loads its hat
// column directly to registers (coalesced LDG.32) and mirrors to smem for the
// delta row-dots — no float4 fill, no LDS hoist.
// ============================================================================
__device__ __forceinline__ float wred_max(float v) {
    #pragma unroll
    for (int o = 16; o > 0; o >>= 1) v = fmaxf(v, __shfl_xor_sync(0xffffffffu, v, o));
    return v;
}
__device__ __forceinline__ float wred_sum(float v) {
    #pragma unroll
    for (int o = 16; o > 0; o >>= 1) v += __shfl_xor_sync(0xffffffffu, v, o);
    return v;
}

__global__ __launch_bounds__(64) void routing_kernel(
    const int* __restrict__ mask,    // (B, S)
    float* __restrict__ out)         // (B, I, E)
{
    __shared__ __align__(16) float hat_sm[S_ * 68];
    __shared__ float sw_sm[64];
    __shared__ __align__(16) float cap_sm[64];
    __shared__ float red_sm[4];

    const int bi   = blockIdx.x;
    const int b    = bi >> 2;
    const int i    = bi & 3;
    const int t    = threadIdx.x;    // 0..63
    const int wid  = t >> 5;
    const int lane = t & 31;

    const float mk = (t < S_ && mask[b * S_ + t] != 0) ? 1.0f : 0.0f;

    const float* hg = g_hat + ((size_t)b * I_ + i) * (S_ * E_);

    // direct column load: h[s] = hat[s][t] (coalesced), mirror to smem rows
    float h[S_];
    #pragma unroll
    for (int s = 0; s < S_; ++s) {
        h[s] = hg[s * E_ + t];
        hat_sm[s * 68 + t] = h[s];
    }
    __syncthreads();

    float cw = 0.0f, cap = 0.0f;

    #pragma unroll
    for (int it = 0; it < 3; ++it) {
        // softmax over all 50 s, then masked to 0 (no renorm)
        float x = (t < S_) ? cw : -1e30f;
        float wm = wred_max(x);
        if (lane == 0) red_sm[wid] = wm;
        __syncthreads();
        float mx = fmaxf(red_sm[0], red_sm[1]);
        float ex = (t < S_) ? __expf(x - mx) : 0.0f;
        float ws = wred_sum(ex);
        if (lane == 0) red_sm[2 + wid] = ws;
        __syncthreads();
        float inv = 1.0f / (red_sm[2] + red_sm[3]);
        sw_sm[t] = ex * inv * mk;      // rows >= 50 never read
        __syncthreads();

        // cap[e=t] = sum_s sw[s] * h[s]   (hat from registers, 2-way chain)
        float c0 = 0.0f, c1 = 0.0f;
        #pragma unroll
        for (int s = 0; s < S_ - 1; s += 2) {
            c0 = fmaf(sw_sm[s],     h[s],     c0);
            c1 = fmaf(sw_sm[s + 1], h[s + 1], c1);
        }
        float c = c0 + c1;

        // squash
        float ns = wred_sum(c * c);
        if (lane == 0) red_sm[wid] = ns;
        __syncthreads();
        float n = red_sm[0] + red_sm[1];
        float scale = (n / (1.0f + n)) * rsqrtf(n + 1e-9f);
        cap = c * scale;

        if (it < 2) {
            cap_sm[t] = cap;
            __syncthreads();
            // delta[s=t] = sum_e hat[t][e] * cap[e]  (smem rows)
            if (t < S_) {
                const float4* h4 = (const float4*)&hat_sm[t * 68];
                const float4* c4 = (const float4*)cap_sm;
                float d0 = 0.0f, d1 = 0.0f;
                #pragma unroll
                for (int e4 = 0; e4 < 16; e4 += 2) {
                    float4 hv = h4[e4], cv = c4[e4];
                    d0 = fmaf(hv.x, cv.x, d0); d0 = fmaf(hv.y, cv.y, d0);
                    d0 = fmaf(hv.z, cv.z, d0); d0 = fmaf(hv.w, cv.w, d0);
                    float4 hv2 = h4[e4 + 1], cv2 = c4[e4 + 1];
                    d1 = fmaf(hv2.x, cv2.x, d1); d1 = fmaf(hv2.y, cv2.y, d1);
                    d1 = fmaf(hv2.z, cv2.z, d1); d1 = fmaf(hv2.w, cv2.w, d1);
                }
                cw += d0 + d1;
            }
            __syncthreads();
        }
    }

    out[((size_t)b * I_ + i) * E_ + t] = cap;
}

extern "C" void kernel_launch(void* const* d_in, const int* in_sizes, int n_in,
                              void* d_out, int out_size)
{
    const float* item = (const float*)d_in[0];   // (4096, 50, 64) fp32
    const int*   mask = (const int*)d_in[1];     // (4096, 50) int32
    const float* w    = (const float*)d_in[2];   // (1, 50, 256, 64) fp32
    float* out = (float*)d_out;                  // (4096, 4, 64) fp32

    const int w4 = (int)(W_N / 4);
    split_w_kernel<<<(w4 + 255) / 256, 256>>>((const float4*)w, w4);

    cudaFuncSetAttribute(hat_mma_kernel, cudaFuncAttributeMaxDynamicSharedMemorySize,
                         SMEM_GEMM);
    hat_mma_kernel<<<dim3(64, 50), 256, SMEM_GEMM>>>(item);
    routing_kernel<<<B_ * I_, 64>>>(mask, out);
}

// round 10
// speedup vs baseline: 2.0261x; 1.0190x over previous
#include <cuda_runtime.h>
#include <cuda_bf16.h>
#include <math.h>
#include <stdint.h>

#define B_ 4096
#define S_ 50
#define I_ 4
#define E_ 64

// hat scratch, layout (B, I, S, E) — fp32, 209.7 MB
__device__ __align__(256) float g_hat[(size_t)B_ * I_ * S_ * E_];

// pre-split bf16 hi/lo copies of w
#define W_N ((size_t)S_ * I_ * E_ * E_)  // 819,200
__device__ __align__(256) __nv_bfloat16 g_w_h[W_N];
__device__ __align__(256) __nv_bfloat16 g_w_l[W_N];

// ============================================================================
// helpers
// ============================================================================
__device__ __forceinline__ uint32_t smem_u32(const void* p) {
    uint32_t a;
    asm("{ .reg .u64 t; cvta.to.shared.u64 t, %1; cvt.u32.u64 %0, t; }" : "=r"(a) : "l"(p));
    return a;
}

__device__ __forceinline__ void ldsm4(uint32_t* r, uint32_t addr) {
    asm volatile("ldmatrix.sync.aligned.m8n8.x4.shared.b16 {%0,%1,%2,%3}, [%4];"
                 : "=r"(r[0]), "=r"(r[1]), "=r"(r[2]), "=r"(r[3]) : "r"(addr));
}

__device__ __forceinline__ void mma_bf16(float* d, const uint32_t* a, uint32_t b0, uint32_t b1) {
    asm volatile("mma.sync.aligned.m16n8k16.row.col.f32.bf16.bf16.f32 "
                 "{%0,%1,%2,%3}, {%4,%5,%6,%7}, {%8,%9}, {%0,%1,%2,%3};"
                 : "+f"(d[0]), "+f"(d[1]), "+f"(d[2]), "+f"(d[3])
                 : "r"(a[0]), "r"(a[1]), "r"(a[2]), "r"(a[3]), "r"(b0), "r"(b1));
}

__device__ __forceinline__ void split_pack(float a, float b, uint32_t& hi, uint32_t& lo) {
    __nv_bfloat16 ha = __float2bfloat16(a);
    __nv_bfloat16 hb = __float2bfloat16(b);
    __nv_bfloat16 la = __float2bfloat16(a - __bfloat162float(ha));
    __nv_bfloat16 lb = __float2bfloat16(b - __bfloat162float(hb));
    __nv_bfloat162 hp = __nv_bfloat162(ha, hb);
    __nv_bfloat162 lp = __nv_bfloat162(la, lb);
    hi = *reinterpret_cast<uint32_t*>(&hp);
    lo = *reinterpret_cast<uint32_t*>(&lp);
}

// ============================================================================
// Kernel 0: split w fp32 -> bf16 hi/lo
// ============================================================================
__global__ __launch_bounds__(256) void split_w_kernel(const float4* __restrict__ src, int n4)
{
    int idx = blockIdx.x * 256 + threadIdx.x;
    if (idx >= n4) return;
    float4 v = src[idx];
    uint32_t h01, l01, h23, l23;
    split_pack(v.x, v.y, h01, l01);
    split_pack(v.z, v.w, h23, l23);
    ((uint2*)g_w_h)[idx] = make_uint2(h01, h23);
    ((uint2*)g_w_l)[idx] = make_uint2(l01, l23);
}

// ----------------------------------------------------------------------------
// smem layout (bytes): B_hi 32K | B_lo 32K | A_hi 8K | A_lo 8K = 80K
// ----------------------------------------------------------------------------
#define SB_H 0
#define SB_L 32768
#define SA_H 65536
#define SA_L 73728
#define SMEM_GEMM 81920

__device__ __forceinline__ uint32_t swz(int row, int colb) {
    return (uint32_t)(row * 128 + (colb ^ ((row & 7) << 4)));
}

// ============================================================================
// Kernel 1: hat = item @ w^T, bf16 split-2 mma.sync, persistent over 4 b-tiles.
// CTA: one s, full m=256, loops 4 b-tiles of 64. B loaded once; A LDG for
// tile i+1 issued before tile i's MMA (register prefetch pipeline).
// 8 warps: 2(b) x 4(m), warp tile 32 x 64. grid = (16, 50)
// ============================================================================
__global__ __launch_bounds__(256, 2) void hat_mma_kernel(
    const float* __restrict__ item)   // (B, S, E) fp32
{
    extern __shared__ __align__(1024) char smem[];
    const uint32_t sb = smem_u32(smem);
    const int t    = threadIdx.x;
    const int lane = t & 31;
    const int wid  = t >> 5;
    const int wy   = wid >> 2;     // 0..1
    const int wx   = wid & 3;      // 0..3
    const int btg  = blockIdx.x;   // 0..15 (groups of 4 b-tiles)
    const int s    = blockIdx.y;

    // per-thread fixed A coords: c -> (row, k0)
    int  ar[4], ak[4];
    #pragma unroll
    for (int c = 0; c < 4; ++c) {
        int f4 = t + c * 256;          // 0..1023
        ar[c] = f4 >> 4;               // 0..63
        ak[c] = (f4 & 15) * 4;         // 0..60
    }

    // ---- B: 256 rows x 64 k, pre-split bf16, loaded ONCE
    {
        const __nv_bfloat16* bh = g_w_h + (size_t)s * (I_ * E_ * E_);
        const __nv_bfloat16* bl = g_w_l + (size_t)s * (I_ * E_ * E_);
        #pragma unroll
        for (int c = 0; c < 8; ++c) {
            int f  = t + c * 256;       // 0..2047 16B chunks
            int r  = f >> 3;            // 0..255
            int ch = f & 7;             // 0..7
            uint32_t off = swz(r, ch * 16);
            size_t g = (size_t)r * E_ + ch * 8;
            *(uint4*)(smem + SB_H + off) = *(const uint4*)(bh + g);
            *(uint4*)(smem + SB_L + off) = *(const uint4*)(bl + g);
        }
    }

    // ---- prefetch A tile 0 into registers
    float4 areg[4];
    {
        const float* ag = item + (size_t)(btg * 4 * 64) * (S_ * E_) + (size_t)s * E_;
        #pragma unroll
        for (int c = 0; c < 4; ++c)
            areg[c] = *(const float4*)(ag + (size_t)ar[c] * (S_ * E_) + ak[c]);
    }

    const int rsub = (lane & 7) + (lane & 8);
    const int csub = (lane >> 4) << 4;
    const size_t bstride = (size_t)I_ * S_ * E_;

    #pragma unroll
    for (int it = 0; it < 4; ++it) {
        const int bt = btg * 4 + it;

        // split + STS A
        #pragma unroll
        for (int c = 0; c < 4; ++c) {
            uint32_t h01, l01, h23, l23;
            split_pack(areg[c].x, areg[c].y, h01, l01);
            split_pack(areg[c].z, areg[c].w, h23, l23);
            uint32_t off = swz(ar[c], ak[c] * 2);
            *(uint2*)(smem + SA_H + off) = make_uint2(h01, h23);
            *(uint2*)(smem + SA_L + off) = make_uint2(l01, l23);
        }
        // prefetch next A tile (overlaps the MMA phase below)
        if (it < 3) {
            const float* ag = item + (size_t)((bt + 1) * 64) * (S_ * E_) + (size_t)s * E_;
            #pragma unroll
            for (int c = 0; c < 4; ++c)
                areg[c] = *(const float4*)(ag + (size_t)ar[c] * (S_ * E_) + ak[c]);
        }
        __syncthreads();

        float acc[2][8][4];
        #pragma unroll
        for (int mi = 0; mi < 2; ++mi)
            #pragma unroll
            for (int j = 0; j < 8; ++j)
                #pragma unroll
                for (int q = 0; q < 4; ++q) acc[mi][j][q] = 0.0f;

        // pass p: 0 = AH*BH, 1 = AH*BL, 2 = AL*BH
        #pragma unroll
        for (int p = 0; p < 3; ++p) {
            const uint32_t abase = sb + ((p == 2) ? SA_L : SA_H);
            const uint32_t bbase = sb + ((p == 1) ? SB_L : SB_H);
            #pragma unroll
            for (int ks = 0; ks < 4; ++ks) {
                const int kb = ks * 32 + csub;
                uint32_t af[2][4], bf[4][4];
                #pragma unroll
                for (int mi = 0; mi < 2; ++mi) {
                    int r = wy * 32 + mi * 16 + rsub;
                    ldsm4(af[mi], abase + swz(r, kb));
                }
                #pragma unroll
                for (int nb = 0; nb < 4; ++nb) {
                    int n = wx * 64 + nb * 16 + rsub;
                    ldsm4(bf[nb], bbase + swz(n, kb));
                }
                #pragma unroll
                for (int mi = 0; mi < 2; ++mi)
                    #pragma unroll
                    for (int j = 0; j < 8; ++j)
                        mma_bf16(acc[mi][j], af[mi], bf[j >> 1][j & 1], bf[j >> 1][2 + (j & 1)]);
            }
        }

        // direct fragment stores
        #pragma unroll
        for (int mi = 0; mi < 2; ++mi) {
            int row = wy * 32 + mi * 16 + (lane >> 2);
            int b   = bt * 64 + row;
            #pragma unroll
            for (int j = 0; j < 8; ++j) {
                int m = wx * 64 + j * 8 + (lane & 3) * 2;
                int i = m >> 6;
                int e = m & 63;
                size_t off = (((size_t)b * I_ + i) * S_ + s) * E_ + e;
                *(float2*)(g_hat + off)               = make_float2(acc[mi][j][0], acc[mi][j][1]);
                *(float2*)(g_hat + off + 8 * bstride) = make_float2(acc[mi][j][2], acc[mi][j][3]);
            }
        }
        __syncthreads();   // A smem reuse barrier
    }
}

// ============================================================================
// Kernel 2: dynamic routing. 64 threads per (b, i). hat column in registers;
// numerically-safe softmax (max-subtracted); 5 syncs/iter.
// ============================================================================
__device__ __forceinline__ float wred_max(float v) {
    #pragma unroll
    for (int o = 16; o > 0; o >>= 1) v = fmaxf(v, __shfl_xor_sync(0xffffffffu, v, o));
    return v;
}
__device__ __forceinline__ float wred_sum(float v) {
    #pragma unroll
    for (int o = 16; o > 0; o >>= 1) v += __shfl_xor_sync(0xffffffffu, v, o);
    return v;
}

__global__ __launch_bounds__(64) void routing_kernel(
    const int* __restrict__ mask,    // (B, S)
    float* __restrict__ out)         // (B, I, E)
{
    __shared__ __align__(16) float hat_sm[S_ * 68];
    __shared__ float sw_sm[64];
    __shared__ __align__(16) float cap_sm[64];
    __shared__ float red_sm[4];

    const int bi   = blockIdx.x;
    const int b    = bi >> 2;
    const int i    = bi & 3;
    const int t    = threadIdx.x;    // 0..63
    const int wid  = t >> 5;
    const int lane = t & 31;

    const float mk = (t < S_ && mask[b * S_ + t] != 0) ? 1.0f : 0.0f;

    const float* hg = g_hat + ((size_t)b * I_ + i) * (S_ * E_);

    // direct column load: h[s] = hat[s][t] (coalesced), mirror to smem rows
    float h[S_];
    #pragma unroll
    for (int s = 0; s < S_; ++s) {
        h[s] = hg[s * E_ + t];
        hat_sm[s * 68 + t] = h[s];
    }

    float cw = 0.0f, cap = 0.0f;
    __syncthreads();

    #pragma unroll
    for (int it = 0; it < 3; ++it) {
        // softmax over all 50 s (max-subtracted), masked to 0 after, no renorm
        float x = (t < S_) ? cw : -1e30f;
        float wm = wred_max(x);
        if (lane == 0) red_sm[wid] = wm;
        __syncthreads();                                       // sync 1
        float mx = fmaxf(red_sm[0], red_sm[1]);
        float ex = (t < S_) ? __expf(x - mx) : 0.0f;
        float ws = wred_sum(ex);
        if (lane == 0) red_sm[2 + wid] = ws;
        __syncthreads();                                       // sync 2
        float inv = 1.0f / (red_sm[2] + red_sm[3]);
        sw_sm[t] = ex * inv * mk;      // rows >= 50 never read
        __syncthreads();                                       // sync 3

        // cap[e=t] = sum_s sw[s] * h[s]   (hat from registers, 2-way chain)
        float c0 = 0.0f, c1 = 0.0f;
        #pragma unroll
        for (int s = 0; s < S_ - 1; s += 2) {
            c0 = fmaf(sw_sm[s],     h[s],     c0);
            c1 = fmaf(sw_sm[s + 1], h[s + 1], c1);
        }
        float c = c0 + c1;

        // squash
        float ns = wred_sum(c * c);
        if (lane == 0) red_sm[wid] = ns;     // red_sm[0..1] reused; fenced by sync 4
        __syncthreads();                                       // sync 4
        float n = red_sm[0] + red_sm[1];
        float scale = (n / (1.0f + n)) * rsqrtf(n + 1e-9f);
        cap = c * scale;

        if (it < 2) {
            cap_sm[t] = cap;
            __syncthreads();                                   // sync 5
            // delta[s=t] = sum_e hat[t][e] * cap[e]
            if (t < S_) {
                const float4* h4 = (const float4*)&hat_sm[t * 68];
                const float4* c4 = (const float4*)cap_sm;
                float d0 = 0.0f, d1 = 0.0f;
                #pragma unroll
                for (int e4 = 0; e4 < 16; e4 += 2) {
                    float4 hv = h4[e4], cv = c4[e4];
                    d0 = fmaf(hv.x, cv.x, d0); d0 = fmaf(hv.y, cv.y, d0);
                    d0 = fmaf(hv.z, cv.z, d0); d0 = fmaf(hv.w, cv.w, d0);
                    float4 hv2 = h4[e4 + 1], cv2 = c4[e4 + 1];
                    d1 = fmaf(hv2.x, cv2.x, d1); d1 = fmaf(hv2.y, cv2.y, d1);
                    d1 = fmaf(hv2.z, cv2.z, d1); d1 = fmaf(hv2.w, cv2.w, d1);
                }
                cw += d0 + d1;
            }
            // no end-of-delta sync: cap_sm/red_sm rewrites are fenced by
            // the next iteration's syncs 1-4 before any conflicting use.
        }
    }

    out[((size_t)b * I_ + i) * E_ + t] = cap;
}

extern "C" void kernel_launch(void* const* d_in, const int* in_sizes, int n_in,
                              void* d_out, int out_size)
{
    const float* item = (const float*)d_in[0];   // (4096, 50, 64) fp32
    const int*   mask = (const int*)d_in[1];     // (4096, 50) int32
    const float* w    = (const float*)d_in[2];   // (1, 50, 256, 64) fp32
    float* out = (float*)d_out;                  // (4096, 4, 64) fp32

    const int w4 = (int)(W_N / 4);
    split_w_kernel<<<(w4 + 255) / 256, 256>>>((const float4*)w, w4);

    cudaFuncSetAttribute(hat_mma_kernel, cudaFuncAttributeMaxDynamicSharedMemorySize,
                         SMEM_GEMM);
    hat_mma_kernel<<<dim3(16, 50), 256, SMEM_GEMM>>>(item);
    routing_kernel<<<B_ * I_, 64>>>(mask, out);
}

// round 11
// speedup vs baseline: 2.1367x; 1.0546x over previous
#include <cuda_runtime.h>
#include <cuda_bf16.h>
#include <math.h>
#include <stdint.h>

#define B_ 4096
#define S_ 50
#define I_ 4
#define E_ 64

// hat scratch, layout (S, B, I*E): hat2[s][b][m] — fp32, 209.7 MB
__device__ __align__(256) float g_hat[(size_t)S_ * B_ * I_ * E_];

// pre-split bf16 hi/lo copies of w
#define W_N ((size_t)S_ * I_ * E_ * E_)  // 819,200
__device__ __align__(256) __nv_bfloat16 g_w_h[W_N];
__device__ __align__(256) __nv_bfloat16 g_w_l[W_N];

// ============================================================================
// helpers
// ============================================================================
__device__ __forceinline__ uint32_t smem_u32(const void* p) {
    uint32_t a;
    asm("{ .reg .u64 t; cvta.to.shared.u64 t, %1; cvt.u32.u64 %0, t; }" : "=r"(a) : "l"(p));
    return a;
}

__device__ __forceinline__ void ldsm4(uint32_t* r, uint32_t addr) {
    asm volatile("ldmatrix.sync.aligned.m8n8.x4.shared.b16 {%0,%1,%2,%3}, [%4];"
                 : "=r"(r[0]), "=r"(r[1]), "=r"(r[2]), "=r"(r[3]) : "r"(addr));
}

__device__ __forceinline__ void mma_bf16(float* d, const uint32_t* a, uint32_t b0, uint32_t b1) {
    asm volatile("mma.sync.aligned.m16n8k16.row.col.f32.bf16.bf16.f32 "
                 "{%0,%1,%2,%3}, {%4,%5,%6,%7}, {%8,%9}, {%0,%1,%2,%3};"
                 : "+f"(d[0]), "+f"(d[1]), "+f"(d[2]), "+f"(d[3])
                 : "r"(a[0]), "r"(a[1]), "r"(a[2]), "r"(a[3]), "r"(b0), "r"(b1));
}

__device__ __forceinline__ void split_pack(float a, float b, uint32_t& hi, uint32_t& lo) {
    __nv_bfloat16 ha = __float2bfloat16(a);
    __nv_bfloat16 hb = __float2bfloat16(b);
    __nv_bfloat16 la = __float2bfloat16(a - __bfloat162float(ha));
    __nv_bfloat16 lb = __float2bfloat16(b - __bfloat162float(hb));
    __nv_bfloat162 hp = __nv_bfloat162(ha, hb);
    __nv_bfloat162 lp = __nv_bfloat162(la, lb);
    hi = *reinterpret_cast<uint32_t*>(&hp);
    lo = *reinterpret_cast<uint32_t*>(&lp);
}

// ============================================================================
// Kernel 0: split w fp32 -> bf16 hi/lo
// ============================================================================
__global__ __launch_bounds__(256) void split_w_kernel(const float4* __restrict__ src, int n4)
{
    int idx = blockIdx.x * 256 + threadIdx.x;
    if (idx >= n4) return;
    float4 v = src[idx];
    uint32_t h01, l01, h23, l23;
    split_pack(v.x, v.y, h01, l01);
    split_pack(v.z, v.w, h23, l23);
    ((uint2*)g_w_h)[idx] = make_uint2(h01, h23);
    ((uint2*)g_w_l)[idx] = make_uint2(l01, l23);
}

// ----------------------------------------------------------------------------
// smem layout (bytes): B_hi 32K | B_lo 32K | A_hi 8K | A_lo 8K = 80K
// ----------------------------------------------------------------------------
#define SB_H 0
#define SB_L 32768
#define SA_H 65536
#define SA_L 73728
#define SMEM_GEMM 81920

__device__ __forceinline__ uint32_t swz(int row, int colb) {
    return (uint32_t)(row * 128 + (colb ^ ((row & 7) << 4)));
}

// ============================================================================
// Kernel 1: hat2[s][b][m] = sum_k item[b,s,k] * w[s,m,k], bf16 split-2.
// CTA: one s, full m=256, loops 4 b-tiles of 64. B loaded once; A register-
// prefetched. Fused precision passes: 12 ldsm + 48 mma per k-step.
// 8 warps: 2(b) x 4(m). grid = (16, 50)
// ============================================================================
__global__ __launch_bounds__(256, 2) void hat_mma_kernel(
    const float* __restrict__ item)   // (B, S, E) fp32
{
    extern __shared__ __align__(1024) char smem[];
    const uint32_t sb = smem_u32(smem);
    const int t    = threadIdx.x;
    const int lane = t & 31;
    const int wid  = t >> 5;
    const int wy   = wid >> 2;     // 0..1
    const int wx   = wid & 3;      // 0..3
    const int btg  = blockIdx.x;   // 0..15
    const int s    = blockIdx.y;

    // per-thread fixed A coords
    int ar[4], ak[4];
    #pragma unroll
    for (int c = 0; c < 4; ++c) {
        int f4 = t + c * 256;
        ar[c] = f4 >> 4;
        ak[c] = (f4 & 15) * 4;
    }

    // ---- B: 256 rows x 64 k, pre-split bf16, loaded ONCE
    {
        const __nv_bfloat16* bh = g_w_h + (size_t)s * (I_ * E_ * E_);
        const __nv_bfloat16* bl = g_w_l + (size_t)s * (I_ * E_ * E_);
        #pragma unroll
        for (int c = 0; c < 8; ++c) {
            int f  = t + c * 256;
            int r  = f >> 3;
            int ch = f & 7;
            uint32_t off = swz(r, ch * 16);
            size_t g = (size_t)r * E_ + ch * 8;
            *(uint4*)(smem + SB_H + off) = *(const uint4*)(bh + g);
            *(uint4*)(smem + SB_L + off) = *(const uint4*)(bl + g);
        }
    }

    // ---- prefetch A tile 0
    float4 areg[4];
    {
        const float* ag = item + (size_t)(btg * 4 * 64) * (S_ * E_) + (size_t)s * E_;
        #pragma unroll
        for (int c = 0; c < 4; ++c)
            areg[c] = *(const float4*)(ag + (size_t)ar[c] * (S_ * E_) + ak[c]);
    }

    const int rsub = (lane & 7) + (lane & 8);
    const int csub = (lane >> 4) << 4;

    #pragma unroll
    for (int it = 0; it < 4; ++it) {
        const int bt = btg * 4 + it;

        // split + STS A
        #pragma unroll
        for (int c = 0; c < 4; ++c) {
            uint32_t h01, l01, h23, l23;
            split_pack(areg[c].x, areg[c].y, h01, l01);
            split_pack(areg[c].z, areg[c].w, h23, l23);
            uint32_t off = swz(ar[c], ak[c] * 2);
            *(uint2*)(smem + SA_H + off) = make_uint2(h01, h23);
            *(uint2*)(smem + SA_L + off) = make_uint2(l01, l23);
        }
        if (it < 3) {   // prefetch next A tile (overlaps MMA phase)
            const float* ag = item + (size_t)((bt + 1) * 64) * (S_ * E_) + (size_t)s * E_;
            #pragma unroll
            for (int c = 0; c < 4; ++c)
                areg[c] = *(const float4*)(ag + (size_t)ar[c] * (S_ * E_) + ak[c]);
        }
        __syncthreads();

        float acc[2][8][4];
        #pragma unroll
        for (int mi = 0; mi < 2; ++mi)
            #pragma unroll
            for (int j = 0; j < 8; ++j)
                #pragma unroll
                for (int q = 0; q < 4; ++q) acc[mi][j][q] = 0.0f;

        // fused passes: per k-step load af_h, af_l, bf<-B_hi (mma hh, lh),
        // then bf<-B_lo (mma hl). 12 ldsm, 48 mma.
        #pragma unroll
        for (int ks = 0; ks < 4; ++ks) {
            const int kb = ks * 32 + csub;
            uint32_t af_h[2][4], af_l[2][4], bf[4][4];
            #pragma unroll
            for (int mi = 0; mi < 2; ++mi) {
                int r = wy * 32 + mi * 16 + rsub;
                ldsm4(af_h[mi], sb + SA_H + swz(r, kb));
                ldsm4(af_l[mi], sb + SA_L + swz(r, kb));
            }
            #pragma unroll
            for (int nb = 0; nb < 4; ++nb) {
                int n = wx * 64 + nb * 16 + rsub;
                ldsm4(bf[nb], sb + SB_H + swz(n, kb));
            }
            #pragma unroll
            for (int mi = 0; mi < 2; ++mi)
                #pragma unroll
                for (int j = 0; j < 8; ++j) {
                    mma_bf16(acc[mi][j], af_h[mi], bf[j >> 1][j & 1], bf[j >> 1][2 + (j & 1)]);
                    mma_bf16(acc[mi][j], af_l[mi], bf[j >> 1][j & 1], bf[j >> 1][2 + (j & 1)]);
                }
            #pragma unroll
            for (int nb = 0; nb < 4; ++nb) {
                int n = wx * 64 + nb * 16 + rsub;
                ldsm4(bf[nb], sb + SB_L + swz(n, kb));
            }
            #pragma unroll
            for (int mi = 0; mi < 2; ++mi)
                #pragma unroll
                for (int j = 0; j < 8; ++j)
                    mma_bf16(acc[mi][j], af_h[mi], bf[j >> 1][j & 1], bf[j >> 1][2 + (j & 1)]);
        }

        // stores: layout (s, b, m) — CTA block is contiguous 64 KB
        const size_t base = ((size_t)s * B_ + bt * 64) * 256;
        #pragma unroll
        for (int mi = 0; mi < 2; ++mi) {
            int row = wy * 32 + mi * 16 + (lane >> 2);
            #pragma unroll
            for (int j = 0; j < 8; ++j) {
                int m = wx * 64 + j * 8 + (lane & 3) * 2;
                size_t off = base + (size_t)row * 256 + m;
                *(float2*)(g_hat + off)            = make_float2(acc[mi][j][0], acc[mi][j][1]);
                *(float2*)(g_hat + off + 8 * 256)  = make_float2(acc[mi][j][2], acc[mi][j][3]);
            }
        }
        __syncthreads();   // A smem reuse barrier
    }
}

// ============================================================================
// Kernel 2: dynamic routing. 64 threads per (b, i). hat column in registers;
// hat2 layout (s, b, m): per-s 256 B contiguous reads, chip-dense across CTAs.
// ============================================================================
__device__ __forceinline__ float wred_max(float v) {
    #pragma unroll
    for (int o = 16; o > 0; o >>= 1) v = fmaxf(v, __shfl_xor_sync(0xffffffffu, v, o));
    return v;
}
__device__ __forceinline__ float wred_sum(float v) {
    #pragma unroll
    for (int o = 16; o > 0; o >>= 1) v += __shfl_xor_sync(0xffffffffu, v, o);
    return v;
}

__global__ __launch_bounds__(64) void routing_kernel(
    const int* __restrict__ mask,    // (B, S)
    float* __restrict__ out)         // (B, I, E)
{
    __shared__ __align__(16) float hat_sm[S_ * 68];
    __shared__ float sw_sm[64];
    __shared__ __align__(16) float cap_sm[64];
    __shared__ float red_sm[4];

    const int bi   = blockIdx.x;
    const int b    = bi >> 2;
    const int i    = bi & 3;
    const int t    = threadIdx.x;    // 0..63
    const int wid  = t >> 5;
    const int lane = t & 31;

    const float mk = (t < S_ && mask[b * S_ + t] != 0) ? 1.0f : 0.0f;

    // hat2[s][b][i*64+t], stride per s = B_*256
    const size_t sstride = (size_t)B_ * 256;
    const float* hg = g_hat + (size_t)b * 256 + i * 64 + t;

    float h[S_];
    #pragma unroll
    for (int s = 0; s < S_; ++s) {
        h[s] = hg[(size_t)s * sstride];
        hat_sm[s * 68 + t] = h[s];
    }

    float cw = 0.0f, cap = 0.0f;
    __syncthreads();

    #pragma unroll
    for (int it = 0; it < 3; ++it) {
        // softmax over all 50 s (max-subtracted), masked to 0 after, no renorm
        float x = (t < S_) ? cw : -1e30f;
        float wm = wred_max(x);
        if (lane == 0) red_sm[wid] = wm;
        __syncthreads();                                       // sync 1
        float mx = fmaxf(red_sm[0], red_sm[1]);
        float ex = (t < S_) ? __expf(x - mx) : 0.0f;
        float ws = wred_sum(ex);
        if (lane == 0) red_sm[2 + wid] = ws;
        __syncthreads();                                       // sync 2
        float inv = 1.0f / (red_sm[2] + red_sm[3]);
        sw_sm[t] = ex * inv * mk;
        __syncthreads();                                       // sync 3

        // cap[e=t] = sum_s sw[s] * h[s]
        float c0 = 0.0f, c1 = 0.0f;
        #pragma unroll
        for (int s = 0; s < S_ - 1; s += 2) {
            c0 = fmaf(sw_sm[s],     h[s],     c0);
            c1 = fmaf(sw_sm[s + 1], h[s + 1], c1);
        }
        float c = c0 + c1;

        // squash
        float ns = wred_sum(c * c);
        if (lane == 0) red_sm[wid] = ns;
        __syncthreads();                                       // sync 4
        float n = red_sm[0] + red_sm[1];
        float scale = (n / (1.0f + n)) * rsqrtf(n + 1e-9f);
        cap = c * scale;

        if (it < 2) {
            cap_sm[t] = cap;
            __syncthreads();                                   // sync 5
            if (t < S_) {
                const float4* h4 = (const float4*)&hat_sm[t * 68];
                const float4* c4 = (const float4*)cap_sm;
                float d0 = 0.0f, d1 = 0.0f;
                #pragma unroll
                for (int e4 = 0; e4 < 16; e4 += 2) {
                    float4 hv = h4[e4], cv = c4[e4];
                    d0 = fmaf(hv.x, cv.x, d0); d0 = fmaf(hv.y, cv.y, d0);
                    d0 = fmaf(hv.z, cv.z, d0); d0 = fmaf(hv.w, cv.w, d0);
                    float4 hv2 = h4[e4 + 1], cv2 = c4[e4 + 1];
                    d1 = fmaf(hv2.x, cv2.x, d1); d1 = fmaf(hv2.y, cv2.y, d1);
                    d1 = fmaf(hv2.z, cv2.z, d1); d1 = fmaf(hv2.w, cv2.w, d1);
                }
                cw += d0 + d1;
            }
        }
    }

    out[((size_t)b * I_ + i) * E_ + t] = cap;
}

extern "C" void kernel_launch(void* const* d_in, const int* in_sizes, int n_in,
                              void* d_out, int out_size)
{
    const float* item = (const float*)d_in[0];   // (4096, 50, 64) fp32
    const int*   mask = (const int*)d_in[1];     // (4096, 50) int32
    const float* w    = (const float*)d_in[2];   // (1, 50, 256, 64) fp32
    float* out = (float*)d_out;                  // (4096, 4, 64) fp32

    const int w4 = (int)(W_N / 4);
    split_w_kernel<<<(w4 + 255) / 256, 256>>>((const float4*)w, w4);

    cudaFuncSetAttribute(hat_mma_kernel, cudaFuncAttributeMaxDynamicSharedMemorySize,
                         SMEM_GEMM);
    hat_mma_kernel<<<dim3(16, 50), 256, SMEM_GEMM>>>(item);
    routing_kernel<<<B_ * I_, 64>>>(mask, out);
}